// round 4
// baseline (speedup 1.0000x reference)
#include <cuda_runtime.h>
#include <cuda_bf16.h>
#include <stdint.h>

#define NB   512      // batch (docs)
#define NS   512      // seq len
#define NV   50265    // vocab
#define PAD  1

// Scratch (device globals only — no allocations allowed)
__device__ int g_dl[NB];                 // doc lengths
__device__ unsigned int g_arrive = 0;    // barrier arrival counter (self-resetting)
__device__ volatile unsigned int g_sense = 0;  // barrier sense flag (flips each replay)

// ---------------------------------------------------------------------------
// Single fused kernel. One block per doc, 512 threads, fully resident
// (148 SMs x 4 blocks >= 512 blocks with __launch_bounds__(512, 4)).
//
// Phase A: compute own doc length, publish, arrive on grid barrier.
// Phase B: zero-fill this row (201 KB of float4 stores) -- hides barrier wait.
// Phase C: spin on sense flip, reduce all doc lengths -> avgdl -> s_add.
// Phase D: O(S^2) term-frequency via broadcast LDS.128, scatter BM25 values.
// ---------------------------------------------------------------------------
__global__ void __launch_bounds__(512, 4) k_fused(const int* __restrict__ ids,
                                                  float* __restrict__ out) {
    __shared__ __align__(16) int toks[NS];
    __shared__ int   red[16];
    __shared__ float s_add;
    __shared__ unsigned int s_sense0;

    int b = blockIdx.x;
    int t = threadIdx.x;

    // ---- Phase A: own doc length -> g_dl[b], then barrier arrive ----
    int my = ids[b * NS + t];           // coalesced, 64 lines/block
    toks[t] = my;

    int cnt = (my != PAD);
    #pragma unroll
    for (int o = 16; o; o >>= 1)
        cnt += __shfl_down_sync(0xffffffffu, cnt, o);
    if ((t & 31) == 0) red[t >> 5] = cnt;
    __syncthreads();

    if (t == 0) {
        int dl = 0;
        #pragma unroll
        for (int i = 0; i < 16; i++) dl += red[i];
        g_dl[b] = dl;
        __threadfence();                         // publish g_dl[b] before arriving
        unsigned int s0 = g_sense;               // read sense BEFORE arriving
        s_sense0 = s0;
        unsigned int a = atomicAdd(&g_arrive, 1u);
        if (a == NB - 1) {                       // last arrival: reset + flip
            g_arrive = 0;
            __threadfence();
            g_sense = s0 ^ 1u;
        }
    }

    // ---- Phase B: zero-fill this row with wide stores (hides barrier) ----
    float* row = out + (size_t)b * NV;
    // (b*NV) % 4 == b % 4  (NV % 4 == 1): rotating 16B alignment.
    int head = (4 - (b & 3)) & 3;
    if (t < head) row[t] = 0.0f;
    float4* r4 = (float4*)(row + head);
    int nvec   = (NV - head) >> 2;
    const float4 z4 = make_float4(0.f, 0.f, 0.f, 0.f);
    for (int i = t; i < nvec; i += 512)
        r4[i] = z4;
    for (int i = head + (nvec << 2) + t; i < NV; i += 512)
        row[i] = 0.0f;

    // ---- Phase C: wait for all doc lengths, compute avgdl / s_add ----
    if (t == 0) {
        unsigned int s0 = s_sense0;
        while (g_sense == s0) { }                // usually already flipped
    }
    __syncthreads();                             // all threads see barrier passed

    int v = g_dl[t];                             // L2 hits (512 ints)
    #pragma unroll
    for (int o = 16; o; o >>= 1)
        v += __shfl_down_sync(0xffffffffu, v, o);
    if ((t & 31) == 0) red[t >> 5] = v;
    __syncthreads();
    if (t == 0) {
        int s = 0;
        #pragma unroll
        for (int i = 0; i < 16; i++) s += red[i];
        float avgdl = (float)s / (float)NB;
        float d_avg = (float)g_dl[b] / avgdl;
        s_add = 1.6f * (1.0f - 0.75f + 0.75f * d_avg);   // k*(1-b+b*d_avg)
    }
    __syncthreads();

    // ---- Phase D: term frequency via broadcast LDS.128 + scatter ----
    int c = 0;
    const int4* t4 = (const int4*)toks;
    #pragma unroll 8
    for (int j = 0; j < NS / 4; j++) {
        int4 q = t4[j];                          // warp-broadcast: conflict-free
        c += (q.x == my) + (q.y == my) + (q.z == my) + (q.w == my);
    }

    if (my != PAD) {
        float cf = (float)c;
        row[my] = cf * 2.6f / (cf + s_add);      // (k+1) = 2.6
    }
}

// ---------------------------------------------------------------------------
extern "C" void kernel_launch(void* const* d_in, const int* in_sizes, int n_in,
                              void* d_out, int out_size) {
    const int* ids = (const int*)d_in[0];
    float*     out = (float*)d_out;
    k_fused<<<NB, 512>>>(ids, out);
}

// round 9
// speedup vs baseline: 1.3571x; 1.3571x over previous
#include <cuda_runtime.h>
#include <cuda_bf16.h>
#include <stdint.h>

#define NB   512      // batch (docs)
#define NS   512      // seq len
#define NV   50265    // vocab
#define PAD  1

// Scratch (device globals only — no allocations allowed)
__device__ int g_dl[NB];    // doc lengths (non-pad token counts)

// ---------------------------------------------------------------------------
// Kernel 1: per-row doc length. 512 blocks x 128 threads, one int4 per thread.
// ---------------------------------------------------------------------------
__global__ void __launch_bounds__(128) k_doclen(const int* __restrict__ ids) {
    int b = blockIdx.x;
    int t = threadIdx.x;
    const int4* row4 = (const int4*)(ids + b * NS);
    int4 q = row4[t];                      // 128 threads x int4 = 512 ints
    int cnt = (q.x != PAD) + (q.y != PAD) + (q.z != PAD) + (q.w != PAD);

    #pragma unroll
    for (int o = 16; o; o >>= 1)
        cnt += __shfl_down_sync(0xffffffffu, cnt, o);

    __shared__ int red[4];
    if ((t & 31) == 0) red[t >> 5] = cnt;
    __syncthreads();
    if (t == 0)
        g_dl[b] = red[0] + red[1] + red[2] + red[3];
}

// ---------------------------------------------------------------------------
// Kernel 2: zero-fill + atomic histogram + BM25 transform. One block per doc,
// 512 threads. The output row itself is the count buffer:
//   1. zero-fill row (float4 STGs)         -- the store-bound term
//   2. fence + sync                        -- zeros ordered before atomics
//   3. old = atomicAdd(&row[tok], 1.0f)    -- exact float counts; leader = old==0
//   4. sync                                -- all atomics performed
//   5. leader reads total via __ldcg (L2), writes f(total)  -- single writer
// No O(S^2) count loop, no token smem staging.
// ---------------------------------------------------------------------------
__global__ void __launch_bounds__(512) k_main(const int* __restrict__ ids,
                                              float* __restrict__ out) {
    __shared__ int   red[16];
    __shared__ float s_add;

    int b = blockIdx.x;
    int t = threadIdx.x;

    int my = ids[b * NS + t];          // own token (coalesced)

    // avgdl partial reduce (k_doclen finished: graph edge orders it).
    int v = g_dl[t];                   // L2 hits
    #pragma unroll
    for (int o = 16; o; o >>= 1)
        v += __shfl_down_sync(0xffffffffu, v, o);
    if ((t & 31) == 0) red[t >> 5] = v;

    // --- zero-fill this row with wide stores ---
    float* row = out + (size_t)b * NV;
    // (b*NV) % 4 == b % 4  (NV % 4 == 1): rotating 16B alignment.
    int head = (4 - (b & 3)) & 3;
    if (t < head) row[t] = 0.0f;
    float4* r4 = (float4*)(row + head);
    int nvec   = (NV - head) >> 2;
    const float4 z4 = make_float4(0.f, 0.f, 0.f, 0.f);
    for (int i = t; i < nvec; i += 512)
        r4[i] = z4;
    int tail = head + (nvec << 2);     // <= 3 remaining scalars
    if (t < NV - tail) row[tail + t] = 0.0f;

    __threadfence();                   // zeros reach L2 before any block atomic
    __syncthreads();                   // also publishes red[]

    // --- atomic histogram into the row; leader election via returned old ---
    bool leader = false;
    if (my != PAD) {
        float old = atomicAdd(&row[my], 1.0f);
        leader = (old == 0.0f);
    }

    // s_add while atomics fly (t0's own atomic already returned above).
    if (t == 0) {
        int s = 0;
        #pragma unroll
        for (int i = 0; i < 16; i++) s += red[i];
        float avgdl = (float)s / (float)NB;
        float d_avg = (float)g_dl[b] / avgdl;
        s_add = 1.6f * (1.0f - 0.75f + 0.75f * d_avg);   // k*(1-b+b*d_avg)
    }
    __syncthreads();   // every thread held its atomic's return => all performed

    // --- BM25 transform: one writer per (row, token) ---
    if (leader) {
        float c = __ldcg(row + my);    // L2 read (L1 may hold stale zero line)
        row[my] = c * 2.6f / (c + s_add);   // (k+1) = 2.6
    }
}

// ---------------------------------------------------------------------------
extern "C" void kernel_launch(void* const* d_in, const int* in_sizes, int n_in,
                              void* d_out, int out_size) {
    const int* ids = (const int*)d_in[0];
    float*     out = (float*)d_out;

    k_doclen<<<NB, 128>>>(ids);
    k_main<<<NB, 512>>>(ids, out);
}